// round 1
// baseline (speedup 1.0000x reference)
#include <cuda_runtime.h>
#include <math.h>

#define D_MODEL 1024
#define NHEADS  16
#define HDIM    64
#define SEQ     4096
#define BATCH   4
#define MROWS   (BATCH * SEQ)   // 16384

// ---------------------------------------------------------------------------
// Scratch (device globals: allocation-free per harness rules)
// ---------------------------------------------------------------------------
__device__ float g_Q[(size_t)MROWS * D_MODEL];
__device__ float g_K[(size_t)MROWS * D_MODEL];
__device__ float g_V[(size_t)MROWS * D_MODEL];
__device__ float g_ATT[(size_t)MROWS * D_MODEL];
__device__ float g_VK[BATCH * NHEADS * 65 * 64];
__device__ float g_cos[SEQ * 32];
__device__ float g_sin[SEQ * 32];

// ---------------------------------------------------------------------------
// RoPE table: cos/sin computed once in fp64 for accuracy
// ---------------------------------------------------------------------------
__global__ void rope_table_kernel() {
    int idx = blockIdx.x * blockDim.x + threadIdx.x;
    if (idx >= SEQ * 32) return;
    int s = idx >> 5;
    int p = idx & 31;
    // freq = 10000^(-(2p)/64)
    double freq = exp(-((double)(2 * p) / 64.0) * 9.210340371976184); // ln(10000)
    double ang = (double)s * freq;
    g_cos[idx] = (float)cos(ang);
    g_sin[idx] = (float)sin(ang);
}

// ---------------------------------------------------------------------------
// Tiled SGEMM: C[M,N] = A[M,K] @ B[K,N], fp32.
// BM=128, BN=128, BK=16, 256 threads, 8x8 microtile per thread.
// ep=1: fuse RoPE (interleaved pairs, per 64-wide head) + ReLU into epilogue.
// ---------------------------------------------------------------------------
#define BM 128
#define BN 128
#define BK 16
#define TM 8
#define TN 8

__global__ __launch_bounds__(256)
void sgemm_ep(const float* __restrict__ A, const float* __restrict__ B,
              float* __restrict__ C, int M, int N, int K, int ep)
{
    __shared__ float As[BK][BM];   // A tile, transposed
    __shared__ float Bs[BK][BN];

    const int brow = blockIdx.y;
    const int bcol = blockIdx.x;
    const int tid  = threadIdx.x;
    const int trow = tid >> 4;     // 0..15
    const int tcol = tid & 15;     // 0..15

    const float* Ab = A + (size_t)brow * BM * K;
    const float* Bb = B + (size_t)bcol * BN;

    // A loads: 128 rows x 16 cols = 512 float4; 2 per thread
    const int a_r = tid >> 2;          // 0..63 (rows a_r, a_r+64)
    const int a_c = (tid & 3) * 4;     // 0,4,8,12
    // B loads: 16 rows x 128 cols = 512 float4; 2 per thread
    const int b_r = tid >> 5;          // 0..7 (rows b_r, b_r+8)
    const int b_c = (tid & 31) * 4;    // 0..124

    float acc[TM][TN];
#pragma unroll
    for (int i = 0; i < TM; i++)
#pragma unroll
        for (int j = 0; j < TN; j++) acc[i][j] = 0.0f;

    float a_frag[TM], b_frag[TN];

    for (int k0 = 0; k0 < K; k0 += BK) {
#pragma unroll
        for (int i = 0; i < 2; i++) {
            float4 t = *(const float4*)(Ab + (size_t)(a_r + i * 64) * K + k0 + a_c);
            As[a_c + 0][a_r + i * 64] = t.x;
            As[a_c + 1][a_r + i * 64] = t.y;
            As[a_c + 2][a_r + i * 64] = t.z;
            As[a_c + 3][a_r + i * 64] = t.w;
        }
#pragma unroll
        for (int i = 0; i < 2; i++) {
            *(float4*)(&Bs[b_r + i * 8][b_c]) =
                *(const float4*)(Bb + (size_t)(k0 + b_r + i * 8) * N + b_c);
        }
        __syncthreads();

#pragma unroll
        for (int kk = 0; kk < BK; kk++) {
#pragma unroll
            for (int i = 0; i < TM; i++) a_frag[i] = As[kk][trow * TM + i];
#pragma unroll
            for (int j = 0; j < TN; j++) b_frag[j] = Bs[kk][tcol * TN + j];
#pragma unroll
            for (int i = 0; i < TM; i++)
#pragma unroll
                for (int j = 0; j < TN; j++)
                    acc[i][j] = fmaf(a_frag[i], b_frag[j], acc[i][j]);
        }
        __syncthreads();
    }

    const int crow0 = brow * BM + trow * TM;
    const int ccol0 = bcol * BN + tcol * TN;

    if (ep == 1) {
        // RoPE (interleaved pairs within each 64-wide head) + ReLU
#pragma unroll
        for (int i = 0; i < TM; i++) {
            int row = crow0 + i;
            int s = row & (SEQ - 1);
#pragma unroll
            for (int j = 0; j < TN; j += 2) {
                int c = ccol0 + j;
                int p = (c & 63) >> 1;       // pair index within head
                float cs = g_cos[s * 32 + p];
                float sn = g_sin[s * 32 + p];
                float x1 = acc[i][j];
                float x2 = acc[i][j + 1];
                float r1 = x1 * cs - x2 * sn;
                float r2 = fmaf(x1, sn, x2 * cs);
                acc[i][j]     = fmaxf(r1, 0.0f);
                acc[i][j + 1] = fmaxf(r2, 0.0f);
            }
        }
    }

#pragma unroll
    for (int i = 0; i < TM; i++) {
        float4* cp = (float4*)(C + (size_t)(crow0 + i) * N + ccol0);
        cp[0] = make_float4(acc[i][0], acc[i][1], acc[i][2], acc[i][3]);
        cp[1] = make_float4(acc[i][4], acc[i][5], acc[i][6], acc[i][7]);
    }
}

// ---------------------------------------------------------------------------
// vk[b,h,e,d] = sum_s vpad[b,h,s,e] * k[b,h,s,d]   (e<64: v; e==64: vpad==1)
// One CTA per (b,h). Outer-product accumulation over 64-row chunks.
// ---------------------------------------------------------------------------
__global__ __launch_bounds__(256)
void vk_kernel()
{
    __shared__ float ks[64][64];
    __shared__ float vs[64][64];

    const int bh = blockIdx.x;
    const int b = bh >> 4;
    const int h = bh & 15;
    const int t = threadIdx.x;
    const int d  = t & 63;     // column of k
    const int eg = t >> 6;     // 0..3: e group (e = eg*16 + j)

    const size_t base = (size_t)b * SEQ * D_MODEL + (size_t)h * 64;

    float acc[16];
#pragma unroll
    for (int j = 0; j < 16; j++) acc[j] = 0.0f;
    float ksum = 0.0f;

    for (int c = 0; c < SEQ / 64; c++) {
        for (int i = t; i < 64 * 64; i += 256) {
            int row = i >> 6, col = i & 63;
            size_t goff = base + (size_t)(c * 64 + row) * D_MODEL + col;
            ks[row][col] = g_K[goff];
            vs[row][col] = g_V[goff];
        }
        __syncthreads();
#pragma unroll 4
        for (int ss = 0; ss < 64; ss++) {
            float kv = ks[ss][d];
            if (eg == 0) ksum += kv;
#pragma unroll
            for (int j = 0; j < 16; j++)
                acc[j] = fmaf(vs[ss][eg * 16 + j], kv, acc[j]);
        }
        __syncthreads();
    }

    float* vkp = g_VK + (size_t)bh * 65 * 64;
#pragma unroll
    for (int j = 0; j < 16; j++)
        vkp[(eg * 16 + j) * 64 + d] = acc[j];
    if (eg == 0)
        vkp[64 * 64 + d] = ksum;
}

// ---------------------------------------------------------------------------
// attn[b,h,l,e] = (sum_d vk[e,d]*q[l,d]) / (sum_d vk[64,d]*q[l,d] + eps)
// grid = (64 bh, 16 l-chunks), 256 threads; one token row per thread.
// Output written as (b*S+l, h*64+e) row-major -> feeds final GEMM directly.
// ---------------------------------------------------------------------------
__global__ __launch_bounds__(256)
void attn_kernel()
{
    __shared__ float vkS[65][64];
    const int bh = blockIdx.x;
    const int b = bh >> 4;
    const int h = bh & 15;
    const int t = threadIdx.x;

    const float* vkp = g_VK + (size_t)bh * 65 * 64;
    for (int i = t; i < 65 * 64; i += 256)
        vkS[i >> 6][i & 63] = vkp[i];
    __syncthreads();

    const int l = blockIdx.y * 256 + t;
    const size_t roff = ((size_t)(b * SEQ + l)) * D_MODEL + (size_t)h * 64;
    const float* qr = g_Q + roff;

    float q[64];
#pragma unroll
    for (int i = 0; i < 16; i++) {
        float4 v4 = ((const float4*)qr)[i];
        q[4 * i + 0] = v4.x; q[4 * i + 1] = v4.y;
        q[4 * i + 2] = v4.z; q[4 * i + 3] = v4.w;
    }

    float denom = 1e-6f;
#pragma unroll
    for (int d = 0; d < 64; d++) denom = fmaf(vkS[64][d], q[d], denom);
    float inv = 1.0f / denom;

    float* orow = g_ATT + roff;
    for (int e = 0; e < 64; e++) {
        float num = 0.0f;
#pragma unroll
        for (int d = 0; d < 64; d++) num = fmaf(vkS[e][d], q[d], num);
        orow[e] = num * inv;
    }
}

// ---------------------------------------------------------------------------
// kernel_launch
// ---------------------------------------------------------------------------
extern "C" void kernel_launch(void* const* d_in, const int* in_sizes, int n_in,
                              void* d_out, int out_size)
{
    const float* x  = (const float*)d_in[0];
    const float* Wq = (const float*)d_in[1];
    const float* Wk = (const float*)d_in[2];
    const float* Wv = (const float*)d_in[3];
    const float* Wo = (const float*)d_in[4];
    float* out = (float*)d_out;

    float *qp, *kp, *vp, *ap;
    cudaGetSymbolAddress((void**)&qp, g_Q);
    cudaGetSymbolAddress((void**)&kp, g_K);
    cudaGetSymbolAddress((void**)&vp, g_V);
    cudaGetSymbolAddress((void**)&ap, g_ATT);

    rope_table_kernel<<<(SEQ * 32 + 255) / 256, 256>>>();

    dim3 grid(D_MODEL / BN, MROWS / BM);
    sgemm_ep<<<grid, 256>>>(x, Wq, qp, MROWS, D_MODEL, D_MODEL, 1);
    sgemm_ep<<<grid, 256>>>(x, Wk, kp, MROWS, D_MODEL, D_MODEL, 1);
    sgemm_ep<<<grid, 256>>>(x, Wv, vp, MROWS, D_MODEL, D_MODEL, 0);

    vk_kernel<<<BATCH * NHEADS, 256>>>();
    attn_kernel<<<dim3(BATCH * NHEADS, SEQ / 256), 256>>>();

    sgemm_ep<<<grid, 256>>>(ap, Wo, out, MROWS, D_MODEL, D_MODEL, 0);
}